// round 6
// baseline (speedup 1.0000x reference)
#include <cuda_runtime.h>

__device__ __forceinline__ float2 cmul(float2 a, float2 b) {
    return make_float2(a.x * b.x - a.y * b.y, a.x * b.y + a.y * b.x);
}

// ---------------------------------------------------------------------------
// Packed f32x2 helpers. Lane0 = real, lane1 = imag.
// ---------------------------------------------------------------------------
__device__ __forceinline__ unsigned long long splat2(float v) {
    unsigned long long r;
    asm("mov.b64 %0, {%1, %1};" : "=l"(r) : "f"(v));
    return r;
}
__device__ __forceinline__ void ffma2(unsigned long long& acc,
                                      unsigned long long a, unsigned long long b) {
    asm("fma.rn.f32x2 %0, %1, %2, %0;" : "+l"(acc) : "l"(a), "l"(b));
}
__device__ __forceinline__ float2 unpack2(unsigned long long v) {
    float2 r;
    asm("mov.b64 {%0, %1}, %2;" : "=f"(r.x), "=f"(r.y) : "l"(v));
    return r;
}

// ---------------------------------------------------------------------------
// Single fused kernel.
//   Per-CTA prep (cheap, fully parallel across SMs):
//     threads 0..23 : 24 gate matrices via precise sincosf -> shared
//     warps 0..7    : propagate 16 basis columns (2 per warp: lanes 0-15
//                     column w, lanes 16-31 column w+8) through 6 layers of
//                     Rot gates (shfl_xor butterflies) + CNOT rings
//                     (computed-source shuffles), writing U directly into sU.
//   Matvec (R1 structure, best measured): 2 batch elements/thread, 16 complex
//   accumulators each (f32x2-packed), LDS.128 matrix row loads, factored
//   rank-1 state s_j = h[j>>2]*l[j&3], sign-butterfly epilogue.
// ---------------------------------------------------------------------------
__global__ __launch_bounds__(256, 2)
void qfused_kernel(const float4* __restrict__ x4, const float* __restrict__ wts,
                   float4* __restrict__ out4, int half) {
    __shared__ float4 sU[16][8];   // sU[j] row = 16 float2 = (Re,Im) of U[k][j], k=0..15
    __shared__ float2 sm[24][4];   // m00, m01, m10, m11 per gate

    int tid  = threadIdx.x;
    int gtid = blockIdx.x * 256 + tid;

    // ---- gate matrices (threads 0..23, precise sincosf) ----
    if (tid < 24) {
        float ph = wts[tid * 3 + 0];
        float th = wts[tid * 3 + 1];
        float om = wts[tid * 3 + 2];
        float st, ct; sincosf(0.5f * th, &st, &ct);
        float sa, ca; sincosf(0.5f * (ph + om), &sa, &ca);
        float sb, cb; sincosf(0.5f * (ph - om), &sb, &cb);
        sm[tid][0] = make_float2( ca * ct, -sa * ct);   //  ep*c
        sm[tid][1] = make_float2(-cb * st, -sb * st);   // -conj(em)*s
        sm[tid][2] = make_float2( cb * st, -sb * st);   //  em*s
        sm[tid][3] = make_float2( ca * ct,  sa * ct);   //  conj(ep)*c
    }

    // ---- per-element prologue (independent of gates; hides LDG latency) ----
    float h0[4], l0[4], h1[4], l1[4];
    {
        float4 xa = x4[gtid];
        float4 xb = x4[gtid + half];
        float c0, s0, c1, s1, c2, s2, c3, s3;
        __sincosf(0.5f * xa.x, &s0, &c0);
        __sincosf(0.5f * xa.y, &s1, &c1);
        __sincosf(0.5f * xa.z, &s2, &c2);
        __sincosf(0.5f * xa.w, &s3, &c3);
        h0[0] = c0 * c1; h0[1] = c0 * s1; h0[2] = s0 * c1; h0[3] = s0 * s1;
        l0[0] = c2 * c3; l0[1] = c2 * s3; l0[2] = s2 * c3; l0[3] = s2 * s3;
        __sincosf(0.5f * xb.x, &s0, &c0);
        __sincosf(0.5f * xb.y, &s1, &c1);
        __sincosf(0.5f * xb.z, &s2, &c2);
        __sincosf(0.5f * xb.w, &s3, &c3);
        h1[0] = c0 * c1; h1[1] = c0 * s1; h1[2] = s0 * c1; h1[3] = s0 * s1;
        l1[0] = c2 * c3; l1[1] = c2 * s3; l1[2] = s2 * c3; l1[3] = s2 * s3;
    }

    __syncthreads();   // gate matrices visible

    // ---- column propagation: warps 0..7, two columns per warp ----
    int wid  = tid >> 5;
    int lane = tid & 31;
    if (wid < 8) {
        int k   = lane & 15;
        int col = wid + ((lane >> 4) << 3);   // lanes 0-15: wid, lanes 16-31: wid+8
        float2 v = make_float2(k == col ? 1.0f : 0.0f, 0.0f);
#pragma unroll
        for (int l = 0; l < 6; ++l) {
#pragma unroll
            for (int w = 0; w < 4; ++w) {
                int g = l * 4 + w;
                float2 m00 = sm[g][0], m01 = sm[g][1], m10 = sm[g][2], m11 = sm[g][3];
                int mask = 8 >> w;
                float px = __shfl_xor_sync(0xffffffffu, v.x, mask);
                float py = __shfl_xor_sync(0xffffffffu, v.y, mask);
                float2 p = make_float2(px, py);
                float2 cv = (k & mask) ? m11 : m00;
                float2 cp = (k & mask) ? m10 : m01;
                float2 a = cmul(cv, v), b = cmul(cp, p);
                v = make_float2(a.x + b.x, a.y + b.y);
            }
            int r = l % 3 + 1;
#pragma unroll
            for (int w = 0; w < 4; ++w) {
                int cmask = 8 >> w;
                int tmask = 8 >> ((w + r) & 3);
                int src = ((k & cmask) ? (k ^ tmask) : k) | (lane & 16);
                float nx = __shfl_sync(0xffffffffu, v.x, src);
                float ny = __shfl_sync(0xffffffffu, v.y, src);
                v = make_float2(nx, ny);
            }
        }
        ((float2*)sU)[col * 16 + k] = v;      // sU[col][k] = U[k][col]
    }
    __syncthreads();   // unitary staged

    // ---- complex matvec t = U s for both elements (f32x2 FFMA2) ----
    unsigned long long acc0[16], acc1[16];
#pragma unroll
    for (int k = 0; k < 16; ++k) { acc0[k] = 0ull; acc1[k] = 0ull; }

#pragma unroll
    for (int j = 0; j < 16; ++j) {
        unsigned long long sj0 = splat2(h0[j >> 2] * l0[j & 3]);
        unsigned long long sj1 = splat2(h1[j >> 2] * l1[j & 3]);
        const ulonglong2* row = reinterpret_cast<const ulonglong2*>(&sU[j][0]);
#pragma unroll
        for (int kk = 0; kk < 8; ++kk) {
            ulonglong2 m = row[kk];            // LDS.128: 2 complex entries
            ffma2(acc0[2 * kk],     m.x, sj0);
            ffma2(acc0[2 * kk + 1], m.y, sj0);
            ffma2(acc1[2 * kk],     m.x, sj1);
            ffma2(acc1[2 * kk + 1], m.y, sj1);
        }
    }

    // ---- probabilities + Z-sign butterfly + store, per element ----
#pragma unroll
    for (int e = 0; e < 2; ++e) {
        const unsigned long long* acc = (e == 0) ? acc0 : acc1;
        float p[16];
#pragma unroll
        for (int k = 0; k < 16; ++k) {
            float2 v = unpack2(acc[k]);
            p[k] = v.x * v.x + v.y * v.y;
        }
        float a8[8], a4[4];
        float q3 = 0.0f, q2 = 0.0f;
#pragma unroll
        for (int i = 0; i < 8; ++i) { a8[i] = p[2 * i] + p[2 * i + 1]; q3 += p[2 * i] - p[2 * i + 1]; }
#pragma unroll
        for (int i = 0; i < 4; ++i) { a4[i] = a8[2 * i] + a8[2 * i + 1]; q2 += a8[2 * i] - a8[2 * i + 1]; }
        float q1 = (a4[0] - a4[1]) + (a4[2] - a4[3]);
        float q0 = (a4[0] + a4[1]) - (a4[2] + a4[3]);
        out4[e == 0 ? gtid : gtid + half] = make_float4(q0, q1, q2, q3);
    }
}

extern "C" void kernel_launch(void* const* d_in, const int* in_sizes, int n_in,
                              void* d_out, int out_size) {
    const float* x   = (const float*)d_in[0];
    const float* wts = (const float*)d_in[1];
    int nx = in_sizes[0];
    if (n_in >= 2 && in_sizes[0] == 72 && in_sizes[1] != 72) {
        wts = (const float*)d_in[0];
        x   = (const float*)d_in[1];
        nx  = in_sizes[1];
    }
    int B = nx / 4;              // 262144
    int half = B / 2;            // 2 elems/thread
    int grid = (half + 255) / 256;

    qfused_kernel<<<grid, 256>>>((const float4*)x, wts, (float4*)d_out, half);
}

// round 7
// speedup vs baseline: 1.0665x; 1.0665x over previous
#include <cuda_runtime.h>

__device__ __forceinline__ float2 cmul(float2 a, float2 b) {
    return make_float2(a.x * b.x - a.y * b.y, a.x * b.y + a.y * b.x);
}

// ---------------------------------------------------------------------------
// Packed f32x2 helpers. Lane0 = real, lane1 = imag.
// ---------------------------------------------------------------------------
__device__ __forceinline__ unsigned long long splat2(float v) {
    unsigned long long r;
    asm("mov.b64 %0, {%1, %1};" : "=l"(r) : "f"(v));
    return r;
}
__device__ __forceinline__ void ffma2(unsigned long long& acc,
                                      unsigned long long a, unsigned long long b) {
    asm("fma.rn.f32x2 %0, %1, %2, %0;" : "+l"(acc) : "l"(a), "l"(b));
}
__device__ __forceinline__ float2 unpack2(unsigned long long v) {
    float2 r;
    asm("mov.b64 {%0, %1}, %2;" : "=f"(r.x), "=f"(r.y) : "l"(v));
    return r;
}

// ---------------------------------------------------------------------------
// Single fused kernel.
//   Per-CTA prep (cheap):
//     threads 0..23 : 24 gate matrices via FAST __sincosf (MUFU) -> shared
//                     (args in [-pi, 2pi]; abs err ~1e-6, fine vs 1e-3 tol)
//     warps 0..7    : propagate 16 basis columns (2 per warp: lanes 0-15
//                     column w, lanes 16-31 column w+8) through 6 layers of
//                     Rot gates (shfl_xor butterflies) + CNOT rings
//                     (computed-source shuffles), writing U directly into sU.
//   Matvec (best measured structure): 2 batch elements/thread, 16 complex
//   accumulators each (f32x2-packed), LDS.128 matrix row loads, factored
//   rank-1 state s_j = h[j>>2]*l[j&3], sign-butterfly epilogue.
// ---------------------------------------------------------------------------
__global__ __launch_bounds__(256, 2)
void qfused_kernel(const float4* __restrict__ x4, const float* __restrict__ wts,
                   float4* __restrict__ out4, int half) {
    __shared__ float4 sU[16][8];   // sU[j] row = 16 float2 = (Re,Im) of U[k][j], k=0..15
    __shared__ float2 sm[24][4];   // m00, m01, m10, m11 per gate

    int tid  = threadIdx.x;
    int gtid = blockIdx.x * 256 + tid;

    // ---- gate matrices (threads 0..23, fast sincos) ----
    if (tid < 24) {
        float ph = wts[tid * 3 + 0];
        float th = wts[tid * 3 + 1];
        float om = wts[tid * 3 + 2];
        float st, ct; __sincosf(0.5f * th, &st, &ct);
        float sa, ca; __sincosf(0.5f * (ph + om), &sa, &ca);
        float sb, cb; __sincosf(0.5f * (ph - om), &sb, &cb);
        sm[tid][0] = make_float2( ca * ct, -sa * ct);   //  ep*c
        sm[tid][1] = make_float2(-cb * st, -sb * st);   // -conj(em)*s
        sm[tid][2] = make_float2( cb * st, -sb * st);   //  em*s
        sm[tid][3] = make_float2( ca * ct,  sa * ct);   //  conj(ep)*c
    }

    // ---- per-element prologue (independent of gates; hides LDG latency) ----
    float h0[4], l0[4], h1[4], l1[4];
    {
        float4 xa = x4[gtid];
        float4 xb = x4[gtid + half];
        float c0, s0, c1, s1, c2, s2, c3, s3;
        __sincosf(0.5f * xa.x, &s0, &c0);
        __sincosf(0.5f * xa.y, &s1, &c1);
        __sincosf(0.5f * xa.z, &s2, &c2);
        __sincosf(0.5f * xa.w, &s3, &c3);
        h0[0] = c0 * c1; h0[1] = c0 * s1; h0[2] = s0 * c1; h0[3] = s0 * s1;
        l0[0] = c2 * c3; l0[1] = c2 * s3; l0[2] = s2 * c3; l0[3] = s2 * s3;
        __sincosf(0.5f * xb.x, &s0, &c0);
        __sincosf(0.5f * xb.y, &s1, &c1);
        __sincosf(0.5f * xb.z, &s2, &c2);
        __sincosf(0.5f * xb.w, &s3, &c3);
        h1[0] = c0 * c1; h1[1] = c0 * s1; h1[2] = s0 * c1; h1[3] = s0 * s1;
        l1[0] = c2 * c3; l1[1] = c2 * s3; l1[2] = s2 * c3; l1[3] = s2 * s3;
    }

    __syncthreads();   // gate matrices visible

    // ---- column propagation: warps 0..7, two columns per warp ----
    int wid  = tid >> 5;
    int lane = tid & 31;
    if (wid < 8) {
        int k   = lane & 15;
        int col = wid + ((lane >> 4) << 3);   // lanes 0-15: wid, lanes 16-31: wid+8
        float2 v = make_float2(k == col ? 1.0f : 0.0f, 0.0f);
#pragma unroll
        for (int l = 0; l < 6; ++l) {
#pragma unroll
            for (int w = 0; w < 4; ++w) {
                int g = l * 4 + w;
                float2 m00 = sm[g][0], m01 = sm[g][1], m10 = sm[g][2], m11 = sm[g][3];
                int mask = 8 >> w;
                float px = __shfl_xor_sync(0xffffffffu, v.x, mask);
                float py = __shfl_xor_sync(0xffffffffu, v.y, mask);
                float2 p = make_float2(px, py);
                float2 cv = (k & mask) ? m11 : m00;
                float2 cp = (k & mask) ? m10 : m01;
                float2 a = cmul(cv, v), b = cmul(cp, p);
                v = make_float2(a.x + b.x, a.y + b.y);
            }
            int r = l % 3 + 1;
#pragma unroll
            for (int w = 0; w < 4; ++w) {
                int cmask = 8 >> w;
                int tmask = 8 >> ((w + r) & 3);
                int src = ((k & cmask) ? (k ^ tmask) : k) | (lane & 16);
                float nx = __shfl_sync(0xffffffffu, v.x, src);
                float ny = __shfl_sync(0xffffffffu, v.y, src);
                v = make_float2(nx, ny);
            }
        }
        ((float2*)sU)[col * 16 + k] = v;      // sU[col][k] = U[k][col]
    }
    __syncthreads();   // unitary staged

    // ---- complex matvec t = U s for both elements (f32x2 FFMA2) ----
    unsigned long long acc0[16], acc1[16];
#pragma unroll
    for (int k = 0; k < 16; ++k) { acc0[k] = 0ull; acc1[k] = 0ull; }

#pragma unroll
    for (int j = 0; j < 16; ++j) {
        unsigned long long sj0 = splat2(h0[j >> 2] * l0[j & 3]);
        unsigned long long sj1 = splat2(h1[j >> 2] * l1[j & 3]);
        const ulonglong2* row = reinterpret_cast<const ulonglong2*>(&sU[j][0]);
#pragma unroll
        for (int kk = 0; kk < 8; ++kk) {
            ulonglong2 m = row[kk];            // LDS.128: 2 complex entries
            ffma2(acc0[2 * kk],     m.x, sj0);
            ffma2(acc0[2 * kk + 1], m.y, sj0);
            ffma2(acc1[2 * kk],     m.x, sj1);
            ffma2(acc1[2 * kk + 1], m.y, sj1);
        }
    }

    // ---- probabilities + Z-sign butterfly + store, per element ----
#pragma unroll
    for (int e = 0; e < 2; ++e) {
        const unsigned long long* acc = (e == 0) ? acc0 : acc1;
        float p[16];
#pragma unroll
        for (int k = 0; k < 16; ++k) {
            float2 v = unpack2(acc[k]);
            p[k] = v.x * v.x + v.y * v.y;
        }
        float a8[8], a4[4];
        float q3 = 0.0f, q2 = 0.0f;
#pragma unroll
        for (int i = 0; i < 8; ++i) { a8[i] = p[2 * i] + p[2 * i + 1]; q3 += p[2 * i] - p[2 * i + 1]; }
#pragma unroll
        for (int i = 0; i < 4; ++i) { a4[i] = a8[2 * i] + a8[2 * i + 1]; q2 += a8[2 * i] - a8[2 * i + 1]; }
        float q1 = (a4[0] - a4[1]) + (a4[2] - a4[3]);
        float q0 = (a4[0] + a4[1]) - (a4[2] + a4[3]);
        out4[e == 0 ? gtid : gtid + half] = make_float4(q0, q1, q2, q3);
    }
}

extern "C" void kernel_launch(void* const* d_in, const int* in_sizes, int n_in,
                              void* d_out, int out_size) {
    const float* x   = (const float*)d_in[0];
    const float* wts = (const float*)d_in[1];
    int nx = in_sizes[0];
    if (n_in >= 2 && in_sizes[0] == 72 && in_sizes[1] != 72) {
        wts = (const float*)d_in[0];
        x   = (const float*)d_in[1];
        nx  = in_sizes[1];
    }
    int B = nx / 4;              // 262144
    int half = B / 2;            // 2 elems/thread
    int grid = (half + 255) / 256;

    qfused_kernel<<<grid, 256>>>((const float4*)x, wts, (float4*)d_out, half);
}

// round 9
// speedup vs baseline: 1.1152x; 1.0457x over previous
#include <cuda_runtime.h>

__device__ __forceinline__ float2 cmul(float2 a, float2 b) {
    return make_float2(a.x * b.x - a.y * b.y, a.x * b.y + a.y * b.x);
}

// ---------------------------------------------------------------------------
// Compile-time schedule: fold the 24 CNOT permutations (GF(2)-linear) into
// the gate shuffle masks. Thread k holds amplitude of state index phi(k);
// CNOT layers update phi symbolically instead of moving data.
//   sh[g]  : shfl_xor partner mask   = phi^{-1}(1<<bit)
//   sel[g] : selector parity mask S  (bit b of phi(k) = parity(k & S))
//   fin[k] : final permutation phi_final(k) for the sU scatter store
// ---------------------------------------------------------------------------
struct PermSched { int sh[24]; int sel[24]; int fin[16]; };

constexpr PermSched make_sched() {
    PermSched P{};
    int F[4] = {1, 2, 4, 8};   // F[b] = phi(e_b)
    int G[4] = {1, 2, 4, 8};   // G[b] = phi^{-1}(e_b)
    int g = 0;
    for (int l = 0; l < 6; ++l) {
        for (int w = 0; w < 4; ++w) {
            int b = 3 - w;
            P.sh[g] = G[b];
            int S = 0;
            for (int j = 0; j < 4; ++j) S |= ((F[j] >> b) & 1) << j;
            P.sel[g] = S;
            ++g;
        }
        int r = l % 3 + 1;
        for (int w = 0; w < 4; ++w) {
            int bc = 3 - w, bt = 3 - ((w + r) & 3);
            // sigma: state gather new[k] = old[k ^ (bit_bc(k) ? 1<<bt : 0)]
            // phi <- sigma o phi ; phi^{-1} <- phi^{-1} o sigma
            for (int b2 = 0; b2 < 4; ++b2)
                if ((F[b2] >> bc) & 1) F[b2] ^= (1 << bt);
            G[bc] ^= G[bt];
        }
    }
    for (int k = 0; k < 16; ++k) {
        int t = 0;
        for (int b = 0; b < 4; ++b) if ((k >> b) & 1) t ^= F[b];
        P.fin[k] = t;
    }
    return P;
}
// __device__ constexpr: constant-evaluated at compile time, addressable from
// device code (plain constexpr globals are host-only under nvcc).
__device__ constexpr PermSched PS = make_sched();

// ---------------------------------------------------------------------------
// Packed f32x2 helpers. Lane0 = real, lane1 = imag.
// ---------------------------------------------------------------------------
__device__ __forceinline__ unsigned long long splat2(float v) {
    unsigned long long r;
    asm("mov.b64 %0, {%1, %1};" : "=l"(r) : "f"(v));
    return r;
}
__device__ __forceinline__ void ffma2(unsigned long long& acc,
                                      unsigned long long a, unsigned long long b) {
    asm("fma.rn.f32x2 %0, %1, %2, %0;" : "+l"(acc) : "l"(a), "l"(b));
}
__device__ __forceinline__ float2 unpack2(unsigned long long v) {
    float2 r;
    asm("mov.b64 {%0, %1}, %2;" : "=f"(r.x), "=f"(r.y) : "l"(v));
    return r;
}

// ---------------------------------------------------------------------------
// Single fused kernel.
//   Prep: threads 0..23 build 24 gate matrices (fast __sincosf) -> shared;
//   warps 0..7 propagate 16 basis columns (2/warp), 24 shuffle-butterfly
//   steps with compile-time folded permutations (no CNOT shuffles), then a
//   statically-permuted scatter into sU.
//   Matvec: 2 batch elements/thread, 16 f32x2 accumulators each, LDS.128
//   matrix row loads, factored rank-1 state, sign-butterfly epilogue.
// ---------------------------------------------------------------------------
__global__ __launch_bounds__(256, 2)
void qfused_kernel(const float4* __restrict__ x4, const float* __restrict__ wts,
                   float4* __restrict__ out4, int half) {
    __shared__ float4 sU[16][8];   // sU[col] row = 16 float2 = (Re,Im) of U[k][col]
    __shared__ float2 sm[24][4];   // m00, m01, m10, m11 per gate

    int tid  = threadIdx.x;
    int gtid = blockIdx.x * 256 + tid;

    // ---- gate matrices (threads 0..23, fast sincos) ----
    if (tid < 24) {
        float ph = wts[tid * 3 + 0];
        float th = wts[tid * 3 + 1];
        float om = wts[tid * 3 + 2];
        float st, ct; __sincosf(0.5f * th, &st, &ct);
        float sa, ca; __sincosf(0.5f * (ph + om), &sa, &ca);
        float sb, cb; __sincosf(0.5f * (ph - om), &sb, &cb);
        sm[tid][0] = make_float2( ca * ct, -sa * ct);   //  ep*c
        sm[tid][1] = make_float2(-cb * st, -sb * st);   // -conj(em)*s
        sm[tid][2] = make_float2( cb * st, -sb * st);   //  em*s
        sm[tid][3] = make_float2( ca * ct,  sa * ct);   //  conj(ep)*c
    }

    // ---- per-element prologue (independent of gates) ----
    float h0[4], l0[4], h1[4], l1[4];
    {
        float4 xa = x4[gtid];
        float4 xb = x4[gtid + half];
        float c0, s0, c1, s1, c2, s2, c3, s3;
        __sincosf(0.5f * xa.x, &s0, &c0);
        __sincosf(0.5f * xa.y, &s1, &c1);
        __sincosf(0.5f * xa.z, &s2, &c2);
        __sincosf(0.5f * xa.w, &s3, &c3);
        h0[0] = c0 * c1; h0[1] = c0 * s1; h0[2] = s0 * c1; h0[3] = s0 * s1;
        l0[0] = c2 * c3; l0[1] = c2 * s3; l0[2] = s2 * c3; l0[3] = s2 * s3;
        __sincosf(0.5f * xb.x, &s0, &c0);
        __sincosf(0.5f * xb.y, &s1, &c1);
        __sincosf(0.5f * xb.z, &s2, &c2);
        __sincosf(0.5f * xb.w, &s3, &c3);
        h1[0] = c0 * c1; h1[1] = c0 * s1; h1[2] = s0 * c1; h1[3] = s0 * s1;
        l1[0] = c2 * c3; l1[1] = c2 * s3; l1[2] = s2 * c3; l1[3] = s2 * s3;
    }

    __syncthreads();   // gate matrices visible

    // ---- column propagation: warps 0..7, two columns per warp ----
    int wid  = tid >> 5;
    int lane = tid & 31;
    if (wid < 8) {
        int k   = lane & 15;
        int col = wid + ((lane >> 4) << 3);   // lanes 0-15: wid, lanes 16-31: wid+8
        float2 v = make_float2(k == col ? 1.0f : 0.0f, 0.0f);
#pragma unroll
        for (int g = 0; g < 24; ++g) {
            float2 m00 = sm[g][0], m01 = sm[g][1], m10 = sm[g][2], m11 = sm[g][3];
            float px = __shfl_xor_sync(0xffffffffu, v.x, PS.sh[g]);
            float py = __shfl_xor_sync(0xffffffffu, v.y, PS.sh[g]);
            float2 p = make_float2(px, py);
            bool hi = (__popc(k & PS.sel[g]) & 1) != 0;
            float2 cv = hi ? m11 : m00;
            float2 cp = hi ? m10 : m01;
            float2 a = cmul(cv, v), b = cmul(cp, p);
            v = make_float2(a.x + b.x, a.y + b.y);
        }
        ((float2*)sU)[col * 16 + PS.fin[k]] = v;   // sU[col][phi_f(k)] = U[phi_f(k)][col]
    }
    __syncthreads();   // unitary staged

    // ---- complex matvec t = U s for both elements (f32x2 FFMA2) ----
    unsigned long long acc0[16], acc1[16];
#pragma unroll
    for (int k = 0; k < 16; ++k) { acc0[k] = 0ull; acc1[k] = 0ull; }

#pragma unroll
    for (int j = 0; j < 16; ++j) {
        unsigned long long sj0 = splat2(h0[j >> 2] * l0[j & 3]);
        unsigned long long sj1 = splat2(h1[j >> 2] * l1[j & 3]);
        const ulonglong2* row = reinterpret_cast<const ulonglong2*>(&sU[j][0]);
#pragma unroll
        for (int kk = 0; kk < 8; ++kk) {
            ulonglong2 m = row[kk];            // LDS.128: 2 complex entries
            ffma2(acc0[2 * kk],     m.x, sj0);
            ffma2(acc0[2 * kk + 1], m.y, sj0);
            ffma2(acc1[2 * kk],     m.x, sj1);
            ffma2(acc1[2 * kk + 1], m.y, sj1);
        }
    }

    // ---- probabilities + Z-sign butterfly + store, per element ----
#pragma unroll
    for (int e = 0; e < 2; ++e) {
        const unsigned long long* acc = (e == 0) ? acc0 : acc1;
        float p[16];
#pragma unroll
        for (int k = 0; k < 16; ++k) {
            float2 v = unpack2(acc[k]);
            p[k] = v.x * v.x + v.y * v.y;
        }
        float a8[8], a4[4];
        float q3 = 0.0f, q2 = 0.0f;
#pragma unroll
        for (int i = 0; i < 8; ++i) { a8[i] = p[2 * i] + p[2 * i + 1]; q3 += p[2 * i] - p[2 * i + 1]; }
#pragma unroll
        for (int i = 0; i < 4; ++i) { a4[i] = a8[2 * i] + a8[2 * i + 1]; q2 += a8[2 * i] - a8[2 * i + 1]; }
        float q1 = (a4[0] - a4[1]) + (a4[2] - a4[3]);
        float q0 = (a4[0] + a4[1]) - (a4[2] + a4[3]);
        out4[e == 0 ? gtid : gtid + half] = make_float4(q0, q1, q2, q3);
    }
}

extern "C" void kernel_launch(void* const* d_in, const int* in_sizes, int n_in,
                              void* d_out, int out_size) {
    const float* x   = (const float*)d_in[0];
    const float* wts = (const float*)d_in[1];
    int nx = in_sizes[0];
    if (n_in >= 2 && in_sizes[0] == 72 && in_sizes[1] != 72) {
        wts = (const float*)d_in[0];
        x   = (const float*)d_in[1];
        nx  = in_sizes[1];
    }
    int B = nx / 4;              // 262144
    int half = B / 2;            // 2 elems/thread
    int grid = (half + 255) / 256;

    qfused_kernel<<<grid, 256>>>((const float4*)x, wts, (float4*)d_out, half);
}